// round 7
// baseline (speedup 1.0000x reference)
#include <cuda_runtime.h>
#include <cuda_bf16.h>

// BoxFilter r=8 (k=17), separable, zero padding, fused in one kernel.
// Tile 64x64 processed as two 32-col halves; EACH half stages only its own
// 80x48 input slab (cp.async zfill) -> horizontal running sums -> s_h ->
// vertical running sums from registers -> STG. The second half's fill is
// issued before the first half's Phase C and waited after it (overlap).
// Smem 27.5 KB (+1 KB driver) -> 6 CTAs/SM (reg-limited at 40), 75% theor occ.
// Input x: [8, 32, 512, 512] f32 (256 images of 512x512), same-shape output.

#define RAD 8
#define KW  (2 * RAD + 1)          // 17
#define TILE_W 64
#define TILE_H 64
#define IN_H  (TILE_H + 2 * RAD)   // 80
#define HALF_W 32
#define HIN_W (HALF_W + 2 * RAD)   // 48 input cols per half
#define IN_PITCH 52                // 13x16B, odd 16B count -> LDS.128 conflict-free
#define HS_PITCH 36                // 9x16B, odd -> conflict-free
#define NTHREADS 256

__device__ __forceinline__ void fill_half(const float* __restrict__ src,
                                          float* s_in, int x0, int y0,
                                          int half, int tid, int H, int W) {
    // 80 rows x 12 float4 = 960 items; gx base 4-aligned -> whole-vec OOB test.
    #pragma unroll
    for (int it = 0; it < 4; it++) {
        const int i = tid + it * NTHREADS;
        if (i < IN_H * 12) {
            const int r  = i / 12;
            const int q  = i - r * 12;
            const int gy = y0 - RAD + r;
            const int gx = x0 - RAD + half * HALF_W + 4 * q;
            const bool ok = ((unsigned)gy < (unsigned)H) &&
                            ((unsigned)gx <= (unsigned)(W - 4));
            const float* gptr = src + (ok ? ((size_t)gy * W + gx) : 0);
            unsigned saddr = (unsigned)__cvta_generic_to_shared(&s_in[r * IN_PITCH + 4 * q]);
            const int sz = ok ? 16 : 0;  // src-size 0 -> zero fill
            asm volatile("cp.async.cg.shared.global [%0], [%1], 16, %2;\n"
                         :: "r"(saddr), "l"(gptr), "r"(sz));
        }
    }
    asm volatile("cp.async.commit_group;\n" ::: "memory");
}

__device__ __forceinline__ void phase_b(const float* s_in, float* s_h, int tid) {
    // 160 tasks: (row 0..79, 16-col strip 0..1). Lane -> consecutive rows.
    if (tid < IN_H * 2) {
        const int row = tid % IN_H;
        const int stp = tid / IN_H;          // 0..1

        const float* p = &s_in[row * IN_PITCH + stp * 16];
        float v[32];
        #pragma unroll
        for (int j = 0; j < 8; j++) {
            float4 q = *reinterpret_cast<const float4*>(p + 4 * j);
            v[4*j + 0] = q.x; v[4*j + 1] = q.y;
            v[4*j + 2] = q.z; v[4*j + 3] = q.w;
        }

        float h[16];
        float sum = 0.0f;
        #pragma unroll
        for (int j = 0; j < KW; j++) sum += v[j];
        h[0] = sum;
        #pragma unroll
        for (int c = 1; c < 16; c++) {
            sum += v[c + KW - 1] - v[c - 1];
            h[c] = sum;
        }

        float4* hp = reinterpret_cast<float4*>(&s_h[row * HS_PITCH + stp * 16]);
        #pragma unroll
        for (int j = 0; j < 4; j++)
            hp[j] = make_float4(h[4*j], h[4*j+1], h[4*j+2], h[4*j+3]);
    }
}

__device__ __forceinline__ void phase_c(const float* s_h, float* __restrict__ dst,
                                        int x0, int y0, int half, int tid, int W) {
    // 128 tasks: (local col 0..31, 16-row seg 0..3). Lanes = consecutive cols.
    if (tid < HALF_W * 4) {
        const float scale = 1.0f / ((float)KW * (float)KW);
        const int col = tid & (HALF_W - 1);
        const int r0  = (tid >> 5) << 4;     // 0,16,32,48

        float v[32];
        #pragma unroll
        for (int j = 0; j < 32; j++)
            v[j] = s_h[(r0 + j) * HS_PITCH + col];

        const int gx = x0 + half * HALF_W + col;

        float sum = 0.0f;
        #pragma unroll
        for (int j = 0; j < KW; j++) sum += v[j];
        dst[(size_t)(y0 + r0) * W + gx] = sum * scale;

        #pragma unroll
        for (int i = 1; i < 16; i++) {
            sum += v[i + KW - 1] - v[i - 1];
            dst[(size_t)(y0 + r0 + i) * W + gx] = sum * scale;
        }
    }
}

__global__ __launch_bounds__(NTHREADS, 6)
void box_filter_fused(const float* __restrict__ in, float* __restrict__ out,
                      int H, int W) {
    __shared__ float s_in[IN_H * IN_PITCH];  // 80*52*4 = 16,640 B
    __shared__ float s_h [IN_H * HS_PITCH]; // 80*36*4 = 11,520 B (total 28,160 B)

    const int img = blockIdx.z;
    const int x0  = blockIdx.x * TILE_W;
    const int y0  = blockIdx.y * TILE_H;
    const int tid = threadIdx.x;

    const float* __restrict__ src = in + (size_t)img * H * W;
    float* __restrict__ dst = out + (size_t)img * H * W;

    // ---- half 0 fill ----
    fill_half(src, s_in, x0, y0, 0, tid, H, W);
    asm volatile("cp.async.wait_group 0;\n" ::: "memory");
    __syncthreads();

    // ---- half 0 horizontal ----
    phase_b(s_in, s_h, tid);
    __syncthreads();          // B0 done: s_h ready, s_in free

    // ---- issue half 1 fill (overlaps with half 0 Phase C) ----
    fill_half(src, s_in, x0, y0, 1, tid, H, W);

    // ---- half 0 vertical + store ----
    phase_c(s_h, dst, x0, y0, 0, tid, W);

    asm volatile("cp.async.wait_group 0;\n" ::: "memory");
    __syncthreads();          // fill1 landed AND C0 finished reading s_h

    // ---- half 1 horizontal ----
    phase_b(s_in, s_h, tid);
    __syncthreads();

    // ---- half 1 vertical + store ----
    phase_c(s_h, dst, x0, y0, 1, tid, W);
}

extern "C" void kernel_launch(void* const* d_in, const int* in_sizes, int n_in,
                              void* d_out, int out_size) {
    const float* x = (const float*)d_in[0];
    float* out = (float*)d_out;

    const int N = 8, C = 32, H = 512, W = 512;
    (void)in_sizes; (void)n_in; (void)out_size;

    dim3 grid(W / TILE_W, H / TILE_H, N * C);  // 8 x 8 x 256 = 16384 blocks
    box_filter_fused<<<grid, NTHREADS>>>(x, out, H, W);
}

// round 8
// speedup vs baseline: 1.0510x; 1.0510x over previous
#include <cuda_runtime.h>
#include <cuda_bf16.h>

// BoxFilter r=8 (k=17), separable, zero padding, fused.
// Each CTA processes TWO y-adjacent 64x64 tiles with a ring-reused 80-row
// input buffer: tile B reuses 16 resident halo rows and its 64 new rows land
// in the 64 dead slots. Second fill overlaps tile A's final vertical pass.
// Per tile: cp.async fill -> two 32-col halves (horizontal running sums into
// small s_h, vertical running sums from registers -> STG), as in the best
// previous kernel. Smem 38.4 KB -> 5 CTAs/SM.
// Input x: [8, 32, 512, 512] f32 (256 images of 512x512), same-shape output.

#define RAD 8
#define KW  (2 * RAD + 1)          // 17
#define TILE_W 64
#define TILE_H 64
#define IN_H  (TILE_H + 2 * RAD)   // 80 resident input rows (ring)
#define IN_PITCH 84                // 21x16B, odd -> LDS.128 conflict-free
#define HALF_W 32
#define HS_PITCH 36                // 9x16B, odd -> conflict-free
#define NTHREADS 256

// Fill `nrows` rows (20 float4 each) starting at global row gy0 into s_in
// slots slot0..slot0+nrows-1 (no wrap needed by construction).
__device__ __forceinline__ void fill_rows(const float* __restrict__ src,
                                          float* s_in, int x0, int gy0,
                                          int slot0, int nrows,
                                          int tid, int H, int W) {
    const int total = nrows * 20;
    int r = tid / 20;
    int q = tid - r * 20;
    #pragma unroll
    for (int it = 0; it < 7; it++) {
        const int idx = tid + it * NTHREADS;
        if (idx < total) {
            const int gy = gy0 + r;
            const int gx = x0 - RAD + 4 * q;
            const bool ok = ((unsigned)gy < (unsigned)H) &&
                            ((unsigned)gx <= (unsigned)(W - 4));
            const float* gptr = src + (ok ? ((size_t)gy * W + gx) : 0);
            unsigned saddr = (unsigned)__cvta_generic_to_shared(
                &s_in[(slot0 + r) * IN_PITCH + 4 * q]);
            const int sz = ok ? 16 : 0;  // src-size 0 -> zero fill
            asm volatile("cp.async.cg.shared.global [%0], [%1], 16, %2;\n"
                         :: "r"(saddr), "l"(gptr), "r"(sz));
        }
        r += 12; q += 16;
        if (q >= 20) { q -= 20; r += 1; }
        if (7 * NTHREADS - NTHREADS >= total && it + 2 > (total + NTHREADS - 1) / NTHREADS) break;
    }
    asm volatile("cp.async.commit_group;\n" ::: "memory");
}

// Horizontal running sums for one 32-col half of one tile.
// tile_off: 0 for tile A (slot = j), 64 for tile B (slot = (j+64) mod 80).
__device__ __forceinline__ void phase_b(const float* s_in, float* s_h,
                                        int c_base, int tile_off, int tid) {
    if (tid < IN_H * 2) {
        const int j   = (tid < IN_H) ? tid : tid - IN_H;  // h-row 0..79
        const int stp = (tid < IN_H) ? 0 : 1;
        int slot = j + tile_off;
        if (slot >= IN_H) slot -= IN_H;

        const float* p = &s_in[slot * IN_PITCH + c_base + stp * 16];
        float v[32];
        #pragma unroll
        for (int k = 0; k < 8; k++) {
            float4 q4 = *reinterpret_cast<const float4*>(p + 4 * k);
            v[4*k + 0] = q4.x; v[4*k + 1] = q4.y;
            v[4*k + 2] = q4.z; v[4*k + 3] = q4.w;
        }

        float h[16];
        float sum = 0.0f;
        #pragma unroll
        for (int k = 0; k < KW; k++) sum += v[k];
        h[0] = sum;
        #pragma unroll
        for (int c = 1; c < 16; c++) {
            sum += v[c + KW - 1] - v[c - 1];
            h[c] = sum;
        }

        float4* hp = reinterpret_cast<float4*>(&s_h[j * HS_PITCH + stp * 16]);
        #pragma unroll
        for (int k = 0; k < 4; k++)
            hp[k] = make_float4(h[4*k], h[4*k+1], h[4*k+2], h[4*k+3]);
    }
}

// Vertical running sums + coalesced store for one 32-col half of one tile.
__device__ __forceinline__ void phase_c(const float* s_h, float* __restrict__ dst,
                                        int x0, int yb, int c_base,
                                        int tid, int W) {
    if (tid < HALF_W * 4) {
        const float scale = 1.0f / ((float)KW * (float)KW);
        const int col = tid & (HALF_W - 1);
        const int r0  = (tid >> 5) << 4;     // 0,16,32,48

        float v[32];
        #pragma unroll
        for (int j = 0; j < 32; j++)
            v[j] = s_h[(r0 + j) * HS_PITCH + col];

        const int gx = x0 + c_base + col;
        float* p = dst + (size_t)(yb + r0) * W + gx;

        float sum = 0.0f;
        #pragma unroll
        for (int j = 0; j < KW; j++) sum += v[j];
        *p = sum * scale;

        #pragma unroll
        for (int i = 1; i < 16; i++) {
            sum += v[i + KW - 1] - v[i - 1];
            p += W;
            *p = sum * scale;
        }
    }
}

__global__ __launch_bounds__(NTHREADS, 6)
void box_filter_fused(const float* __restrict__ in, float* __restrict__ out,
                      int H, int W) {
    __shared__ float s_in[IN_H * IN_PITCH];   // 80*84*4 = 26,880 B (ring)
    __shared__ float s_h [IN_H * HS_PITCH];   // 80*36*4 = 11,520 B (38.4 KB total)

    const int img = blockIdx.z;
    const int x0  = blockIdx.x * TILE_W;
    const int y0  = blockIdx.y * (2 * TILE_H);    // pair base: 0,128,256,384
    const int tid = threadIdx.x;

    const float* __restrict__ src = in + (size_t)img * H * W;
    float* __restrict__ dst = out + (size_t)img * H * W;

    // ---- fill chunk 0: 80 rows (tile A input), slots 0..79 ----
    fill_rows(src, s_in, x0, y0 - RAD, 0, IN_H, tid, H, W);
    asm volatile("cp.async.wait_group 0;\n" ::: "memory");
    __syncthreads();

    // ---- tile A (rows y0..y0+63) ----
    phase_b(s_in, s_h, 0, 0, tid);          // half 0 horizontal
    __syncthreads();
    phase_c(s_h, dst, x0, y0, 0, tid, W);   // half 0 vertical
    __syncthreads();
    phase_b(s_in, s_h, HALF_W, 0, tid);     // half 1 horizontal (last s_in read)
    __syncthreads();

    // ---- fill chunk 1: 64 new rows (y0+72..y0+135) into dead slots 0..63 ----
    // Overlaps tile A's half-1 vertical pass.
    fill_rows(src, s_in, x0, y0 + TILE_H + RAD, 0, TILE_H, tid, H, W);

    phase_c(s_h, dst, x0, y0, HALF_W, tid, W);   // tile A half 1 vertical

    asm volatile("cp.async.wait_group 0;\n" ::: "memory");
    __syncthreads();

    // ---- tile B (rows y0+64..y0+127); s_in ring offset 64 ----
    phase_b(s_in, s_h, 0, TILE_H, tid);
    __syncthreads();
    phase_c(s_h, dst, x0, y0 + TILE_H, 0, tid, W);
    __syncthreads();
    phase_b(s_in, s_h, HALF_W, TILE_H, tid);
    __syncthreads();
    phase_c(s_h, dst, x0, y0 + TILE_H, HALF_W, tid, W);
}

extern "C" void kernel_launch(void* const* d_in, const int* in_sizes, int n_in,
                              void* d_out, int out_size) {
    const float* x = (const float*)d_in[0];
    float* out = (float*)d_out;

    const int N = 8, C = 32, H = 512, W = 512;
    (void)in_sizes; (void)n_in; (void)out_size;

    dim3 grid(W / TILE_W, H / (2 * TILE_H), N * C);  // 8 x 4 x 256 = 8192 CTAs
    box_filter_fused<<<grid, NTHREADS>>>(x, out, H, W);
}